// round 2
// baseline (speedup 1.0000x reference)
#include <cuda_runtime.h>
#include <cstdint>

// y[e, o] = sum_i weight[weight_idx[e], o, i] * values[input_idx[e], i]
// E edges, D_IN = D_OUT = 16.
//
// Layout: 16 lanes cooperate on one edge (2 edges per warp).
//   lane o: loads weight row o (16 floats, 4x float4), one x element,
//           broadcasts x via shfl within the 16-lane segment,
//           computes y[o], writes coalesced.

#define D 16

__global__ __launch_bounds__(256) void edge_linear_kernel(
    const float* __restrict__ values,     // [N_POOL, 16]
    const float4* __restrict__ weight4,   // [N_W, 16, 16] viewed as float4 (64 per matrix)
    const int* __restrict__ input_idx,    // [E]
    const int* __restrict__ weight_idx,   // [E]
    float* __restrict__ out,              // [E, 16]
    int E)
{
    const int gtid = blockIdx.x * blockDim.x + threadIdx.x;
    const int edge = gtid >> 4;
    const int lane = threadIdx.x & 15;   // output index o
    if (edge >= E) return;

    const int ii = __ldg(&input_idx[edge]);
    const int wi = __ldg(&weight_idx[edge]);

    // x element for this lane (16 lanes -> contiguous 64B, coalesced)
    const float xl = __ldg(&values[(size_t)ii * D + lane]);

    // weight row `lane`: 4x float4 = 64B. The 16 lanes together cover the
    // contiguous 1KB matrix.
    const float4* wrow = weight4 + (size_t)wi * (D * D / 4) + lane * 4;
    const float4 a = __ldg(&wrow[0]);
    const float4 b = __ldg(&wrow[1]);
    const float4 c = __ldg(&wrow[2]);
    const float4 d = __ldg(&wrow[3]);

    float wr[D] = {a.x, a.y, a.z, a.w,
                   b.x, b.y, b.z, b.w,
                   c.x, c.y, c.z, c.w,
                   d.x, d.y, d.z, d.w};

    float acc = 0.0f;
#pragma unroll
    for (int i = 0; i < D; i++) {
        // width=16: broadcast from lane i within this 16-lane segment
        const float xi = __shfl_sync(0xFFFFFFFFu, xl, i, 16);
        acc = fmaf(wr[i], xi, acc);
    }

    out[(size_t)edge * D + lane] = acc;
}

extern "C" void kernel_launch(void* const* d_in, const int* in_sizes, int n_in,
                              void* d_out, int out_size)
{
    const float*  values     = (const float*)d_in[0];   // [N_POOL*16] f32
    const float4* weight4    = (const float4*)d_in[1];  // [N_W*256] f32 as float4
    const int*    input_idx  = (const int*)d_in[2];     // [E] int32
    const int*    weight_idx = (const int*)d_in[3];     // [E] int32
    float*        out        = (float*)d_out;           // [E*16] f32

    const int E = in_sizes[2];

    const int threads = 256;
    const long long total = (long long)E * 16;
    const int blocks = (int)((total + threads - 1) / threads);

    edge_linear_kernel<<<blocks, threads>>>(values, weight4, input_idx,
                                            weight_idx, out, E);
}